// round 10
// baseline (speedup 1.0000x reference)
#include <cuda_runtime.h>

#define NN   500000
#define EE   8000000
#define DD   10
#define GG   5000
#define SROW 11                  // smem row stride: 10 features -> 10 consecutive banks
#define BN_EPS 1e-5f
#define NBLK 148
#define NHB  20
#define NHT  256

// ---- scratch (no allocations allowed) ----
__device__ int   d_is64;
__device__ float d_parts[NBLK][GG * DD];   // per-block partial accumulators (~29.6MB)
__device__ float d_stats[4 * 2 * DD];      // per-stage {sum[10], sumsq[10]}
__device__ float d_t[GG * DD];             // pre-BN activations
__device__ float d_res[GG * DD];           // residual (y2)

// ---- init: dtype detect + zero stats (no races: stats only written by later k_stage) ----
__global__ void k_init(const int* __restrict__ ei) {
    if (threadIdx.x == 0) {
        int is64 = 1;
        #pragma unroll
        for (int k = 1; k < 64; k += 2)
            if (ei[k] != 0) { is64 = 0; break; }
        d_is64 = is64;
    }
    if (threadIdx.x < 4 * 2 * DD) d_stats[threadIdx.x] = 0.f;
}

// ---- edge scatter: feature-across-lanes, SMEM-privatized, shift-indexed dtypes ----
// lane = 10*j + d handles feature d of edge (e+j); one ATOMS instr per 3 edges,
// banks (gid*11+d)%32 are consecutive within an edge -> near conflict-free.
__global__ void __launch_bounds__(1024, 1) k_edge(const float* __restrict__ x,
                                                  const int* __restrict__ ei32,
                                                  const float* __restrict__ attr,
                                                  const int* __restrict__ b32) {
    extern __shared__ float sg[];          // GG * SROW floats = 220,000 B
    for (int i = threadIdx.x; i < GG * SROW; i += 1024) sg[i] = 0.f;
    __syncthreads();

    const int s = d_is64;                  // 0: int32 buffers, 1: int64 (read low words)
    const int chunk = (EE + NBLK - 1) / NBLK;
    const int e0 = blockIdx.x * chunk;
    const int e1 = (e0 + chunk < EE) ? e0 + chunk : EE;
    const int wid = threadIdx.x >> 5, lane = threadIdx.x & 31;
    const int ws  = (chunk + 31) / 32;     // edges per warp
    const int we0 = e0 + wid * ws;
    const int we1 = (we0 + ws < e1) ? we0 + ws : e1;

    const int j = lane / 10;               // 0..2 active, 3 -> lanes 30,31 idle
    const int d = lane - j * 10;

    #pragma unroll 2
    for (int e = we0; e < we1; e += 3) {
        int eidx = e + j;
        bool on = (j < 3) && (eidx < we1);
        if (on) {
            int   src = ei32[(size_t)eidx << s];
            int   dst = ei32[((size_t)EE + (size_t)eidx) << s];
            float w   = attr[eidx];
            int   gid = b32[(size_t)dst << s];
            float xv  = x[src * DD + d];
            atomicAdd(&sg[gid * SROW + d], xv * w);
        }
    }
    __syncthreads();
    // flush: plain coalesced stores into this block's private partial (no atomics)
    float* part = d_parts[blockIdx.x];
    for (int i = threadIdx.x; i < GG * DD; i += 1024) {
        int g = i / DD, dd = i - g * DD;
        part[i] = sg[g * SROW + dd];
    }
}

// ---- MLP head stage kernel (5 launches; kernel boundaries = global sync) ----
// s=0: y=pool (reduce 148 partials; count via binary search); t=fc1(y);  stats0
// s=1..3: y=relu(bn_{s-1}(t)) [+res logic];                   t=lin(y);  stats_s
// s=4: y=relu(bn3(t)+res);                                    out=fco(y)
__global__ void __launch_bounds__(NHT, 1) k_stage(
    int s,
    const float* __restrict__ W,   const float* __restrict__ bias,
    const float* __restrict__ gpr, const float* __restrict__ bpr,
    const int*   __restrict__ bv,                                   // batch (32-bit view), s=0
    float* __restrict__ outp)                                       // s=4
{
    __shared__ float sW[DD * DD], sb[DD], sgm[DD], sbt[DD], sst[2 * DD];
    __shared__ float sred[NHT / 32][2 * DD];
    const int tid = threadIdx.x;
    const int wid = tid >> 5, lid = tid & 31;
    const int g = blockIdx.x * NHT + tid;
    const bool act = (g < GG);

    if (s < 4) {
        if (tid < DD * DD) sW[tid] = W[tid];
        if (tid < DD) sb[tid] = bias[tid];
    } else {
        if (tid < DD) sW[tid] = W[tid];
        if (tid == 0) sb[0] = bias[0];
    }
    if (s >= 1) {
        if (tid < DD) { sgm[tid] = gpr[tid]; sbt[tid] = bpr[tid]; }
        if (tid < 2 * DD) sst[tid] = d_stats[(s - 1) * 2 * DD + tid];
    }
    __syncthreads();

    float y[DD];
    if (s == 0) {
        if (act) {
            const int sh = d_is64;
            // node count of graph g in sorted batch via two binary searches
            int lo = 0, hi = NN;
            while (lo < hi) { int mid = (lo + hi) >> 1; if (bv[(size_t)mid << sh] <  g) lo = mid + 1; else hi = mid; }
            int lb = lo;
            lo = 0; hi = NN;
            while (lo < hi) { int mid = (lo + hi) >> 1; if (bv[(size_t)mid << sh] <= g) lo = mid + 1; else hi = mid; }
            int c = lo - lb; if (c < 1) c = 1;
            float inv = 1.f / (float)c;
            float acc[DD];
            #pragma unroll
            for (int dd = 0; dd < DD; dd++) acc[dd] = 0.f;
            for (int p = 0; p < NBLK; p++) {
                #pragma unroll
                for (int dd = 0; dd < DD; dd++) acc[dd] += d_parts[p][g * DD + dd];
            }
            #pragma unroll
            for (int dd = 0; dd < DD; dd++) y[dd] = acc[dd] * inv;
        } else {
            #pragma unroll
            for (int dd = 0; dd < DD; dd++) y[dd] = 0.f;
        }
    } else {
        #pragma unroll
        for (int o = 0; o < DD; o++) {
            float t = act ? d_t[g * DD + o] : 0.f;
            float m = sst[o] * (1.f / GG);
            float q = sst[DD + o] * (1.f / GG);
            float v = q - m * m;
            float val = sgm[o] * (t - m) * rsqrtf(v + BN_EPS) + sbt[o];
            if (s == 4 && act) val += d_res[g * DD + o];
            y[o] = fmaxf(val, 0.f);
        }
        if (s == 2 && act) {
            #pragma unroll
            for (int o = 0; o < DD; o++) d_res[g * DD + o] = y[o];
        }
    }

    if (s == 4) {
        if (act) {
            float a = sb[0];
            #pragma unroll
            for (int dd = 0; dd < DD; dd++) a = fmaf(y[dd], sW[dd], a);
            outp[g] = a;
        }
        return;
    }

    float o_[DD];
    #pragma unroll
    for (int o = 0; o < DD; o++) {
        float a = sb[o];
        #pragma unroll
        for (int dd = 0; dd < DD; dd++) a = fmaf(sW[o * DD + dd], y[dd], a);
        o_[o] = act ? a : 0.f;
        if (act) d_t[g * DD + o] = a;
    }

    float ls[DD], lq[DD];
    #pragma unroll
    for (int o = 0; o < DD; o++) {
        ls[o] = o_[o]; lq[o] = o_[o] * o_[o];
        #pragma unroll
        for (int off = 16; off > 0; off >>= 1) {
            ls[o] += __shfl_xor_sync(0xffffffffu, ls[o], off);
            lq[o] += __shfl_xor_sync(0xffffffffu, lq[o], off);
        }
    }
    if (lid < DD)          sred[wid][lid] = ls[lid];
    else if (lid < 2 * DD) sred[wid][lid] = lq[lid - DD];
    __syncthreads();
    if (tid < 2 * DD) {
        float a = 0.f;
        #pragma unroll
        for (int w = 0; w < NHT / 32; w++) a += sred[w][tid];
        atomicAdd(&d_stats[s * 2 * DD + tid], a);
    }
}

extern "C" void kernel_launch(void* const* d_in, const int* in_sizes, int n_in,
                              void* d_out, int out_size) {
    const float* x     = (const float*)d_in[0];
    const int*   ei32  = (const int*)d_in[1];
    const float* attr  = (const float*)d_in[2];
    const int*   b32   = (const int*)d_in[3];
    const float* fc1_w  = (const float*)d_in[4],  *fc1_b  = (const float*)d_in[5];
    const float* fc2_w  = (const float*)d_in[6],  *fc2_b  = (const float*)d_in[7];
    const float* rfc1_w = (const float*)d_in[8],  *rfc1_b = (const float*)d_in[9];
    const float* rfc2_w = (const float*)d_in[10], *rfc2_b = (const float*)d_in[11];
    const float* fco_w  = (const float*)d_in[12], *fco_b  = (const float*)d_in[13];
    const float* bn1_g  = (const float*)d_in[14], *bn1_b  = (const float*)d_in[15];
    const float* bn2_g  = (const float*)d_in[16], *bn2_b  = (const float*)d_in[17];
    const float* rbn1_g = (const float*)d_in[18], *rbn1_b = (const float*)d_in[19];
    const float* rbn2_g = (const float*)d_in[20], *rbn2_b = (const float*)d_in[21];
    float* out = (float*)d_out;

    static const int SMEM_EDGE = GG * SROW * (int)sizeof(float);   // 220,000 B
    cudaFuncSetAttribute(k_edge, cudaFuncAttributeMaxDynamicSharedMemorySize, SMEM_EDGE);

    k_init <<<1, 128>>>(ei32);
    k_edge <<<NBLK, 1024, SMEM_EDGE>>>(x, ei32, attr, b32);

    k_stage<<<NHB, NHT>>>(0, fc1_w,  fc1_b,  nullptr, nullptr, b32,     nullptr);
    k_stage<<<NHB, NHT>>>(1, fc2_w,  fc2_b,  bn1_g,  bn1_b,  nullptr, nullptr);
    k_stage<<<NHB, NHT>>>(2, rfc1_w, rfc1_b, bn2_g,  bn2_b,  nullptr, nullptr);
    k_stage<<<NHB, NHT>>>(3, rfc2_w, rfc2_b, rbn1_g, rbn1_b, nullptr, nullptr);
    k_stage<<<NHB, NHT>>>(4, fco_w,  fco_b,  rbn2_g, rbn2_b, nullptr, out);
}

// round 13
// speedup vs baseline: 1.1744x; 1.1744x over previous
#include <cuda_runtime.h>

#define NN   500000
#define EE   8000000
#define DD   10
#define GG   5000
#define CAP  2048                // slots per gid; overflow handled losslessly via fallback
#define SL   4                   // warp-slices per gid in gather
#define BN_EPS 1e-5f
#define NHB  20
#define NHT  256

// ---- scratch (no allocations allowed) ----
__device__ int    d_is64;
__device__ int    d_cnt[GG];               // edges per gid (scatter cursors)
__device__ float2 d_sorted[GG * CAP];      // {w, src-as-float} grouped by gid (80MB)
__device__ float  d_gacc[GG * DD];
__device__ float  d_stats[4 * 2 * DD];
__device__ float  d_t[GG * DD];
__device__ float  d_res[GG * DD];

// ---- init: dtype detect + zero counters/accumulators/stats ----
__global__ void k_init(const int* __restrict__ ei) {
    int i = blockIdx.x * blockDim.x + threadIdx.x;
    if (i == 0) {
        int is64 = 1;
        #pragma unroll
        for (int k = 1; k < 64; k += 2)
            if (ei[k] != 0) { is64 = 0; break; }
        d_is64 = is64;
    }
    if (i < GG)         d_cnt[i]   = 0;
    if (i < GG * DD)    d_gacc[i]  = 0.f;
    if (i < 4 * 2 * DD) d_stats[i] = 0.f;
}

// ---- phase A: counting-scatter edges into per-gid buckets ----
// Overflow (pos >= CAP, ~0.06% of edges worst-case) goes directly into d_gacc:
// lossless for any edge distribution.
__global__ void __launch_bounds__(512) k_scat(const float* __restrict__ x,
                                              const int* __restrict__ ei32,
                                              const float* __restrict__ attr,
                                              const int* __restrict__ b32) {
    int e = blockIdx.x * blockDim.x + threadIdx.x;
    if (e >= EE) return;
    const int s = d_is64;                      // 1: int64 buffers -> read low 32-bit words
    int   src = ei32[(size_t)e << s];
    int   dst = ei32[((size_t)EE + (size_t)e) << s];
    float w   = attr[e];
    int   gid = __ldg(&b32[(size_t)dst << s]);
    int   pos = atomicAdd(&d_cnt[gid], 1);
    if (pos < CAP) {
        d_sorted[(size_t)gid * CAP + pos] = make_float2(w, __int_as_float(src));
    } else {
        const float* xr = x + (size_t)src * DD;
        float* gr = d_gacc + (size_t)gid * DD;
        #pragma unroll
        for (int d = 0; d < DD; d++) atomicAdd(gr + d, xr[d] * w);
    }
}

// ---- phase B: atomic-free accumulation; warp-slice per gid, feature-across-lanes ----
__global__ void __launch_bounds__(1024, 1) k_gath(const float* __restrict__ x) {
    int wg   = (blockIdx.x * 1024 + threadIdx.x) >> 5;   // global warp id
    int lane = threadIdx.x & 31;
    int gid   = wg >> 2;                                 // SL = 4
    int slice = wg & 3;
    if (gid >= GG) return;

    int cnt = d_cnt[gid]; if (cnt > CAP) cnt = CAP;      // overflow already in d_gacc
    int per = (cnt + SL - 1) / SL;
    int i0 = slice * per;
    int i1 = i0 + per; if (i1 > cnt) i1 = cnt;

    int j = lane / 10;                                   // 0..2 active, j==3 idle (lanes 30,31)
    int d = lane - j * 10;

    const float2* row = d_sorted + (size_t)gid * CAP;
    float acc = 0.f;
    if (j < 3) {
        #pragma unroll 4
        for (int i = i0 + j; i < i1; i += 3) {
            float2 rec = row[i];                          // broadcast within 10-lane group
            int src = __float_as_int(rec.y);
            acc = fmaf(rec.x, x[src * DD + d], acc);
        }
    }
    // combine the three j-groups onto lanes 0..9
    float v1 = __shfl_sync(0xffffffffu, acc, d + 10);
    float v2 = __shfl_sync(0xffffffffu, acc, d + 20);
    if (lane < 10)
        atomicAdd(&d_gacc[gid * DD + lane], acc + v1 + v2);   // 200k lanes total: negligible
}

// ---- MLP head stage kernel (5 launches; kernel boundaries = global sync) ----
__global__ void __launch_bounds__(NHT, 1) k_stage(
    int s,
    const float* __restrict__ W,   const float* __restrict__ bias,
    const float* __restrict__ gpr, const float* __restrict__ bpr,
    const int*   __restrict__ bv,                                   // batch 32-bit view (s=0)
    float* __restrict__ outp)                                       // s=4
{
    __shared__ float sW[DD * DD], sb[DD], sgm[DD], sbt[DD], sst[2 * DD];
    __shared__ float sred[NHT / 32][2 * DD];
    const int tid = threadIdx.x;
    const int wid = tid >> 5, lid = tid & 31;
    const int g = blockIdx.x * NHT + tid;
    const bool act = (g < GG);

    if (s < 4) {
        if (tid < DD * DD) sW[tid] = W[tid];
        if (tid < DD) sb[tid] = bias[tid];
    } else {
        if (tid < DD) sW[tid] = W[tid];
        if (tid == 0) sb[0] = bias[0];
    }
    if (s >= 1) {
        if (tid < DD) { sgm[tid] = gpr[tid]; sbt[tid] = bpr[tid]; }
        if (tid < 2 * DD) sst[tid] = d_stats[(s - 1) * 2 * DD + tid];
    }
    __syncthreads();

    float y[DD];
    if (s == 0) {
        if (act) {
            const int sh = d_is64;
            int lo = 0, hi = NN;                 // node count of graph g (sorted batch)
            while (lo < hi) { int mid = (lo + hi) >> 1; if (bv[(size_t)mid << sh] <  g) lo = mid + 1; else hi = mid; }
            int lb = lo;
            lo = 0; hi = NN;
            while (lo < hi) { int mid = (lo + hi) >> 1; if (bv[(size_t)mid << sh] <= g) lo = mid + 1; else hi = mid; }
            int c = lo - lb; if (c < 1) c = 1;
            float inv = 1.f / (float)c;
            #pragma unroll
            for (int dd = 0; dd < DD; dd++) y[dd] = d_gacc[g * DD + dd] * inv;
        } else {
            #pragma unroll
            for (int dd = 0; dd < DD; dd++) y[dd] = 0.f;
        }
    } else {
        #pragma unroll
        for (int o = 0; o < DD; o++) {
            float t = act ? d_t[g * DD + o] : 0.f;
            float m = sst[o] * (1.f / GG);
            float q = sst[DD + o] * (1.f / GG);
            float v = q - m * m;
            float val = sgm[o] * (t - m) * rsqrtf(v + BN_EPS) + sbt[o];
            if (s == 4 && act) val += d_res[g * DD + o];
            y[o] = fmaxf(val, 0.f);
        }
        if (s == 2 && act) {
            #pragma unroll
            for (int o = 0; o < DD; o++) d_res[g * DD + o] = y[o];
        }
    }

    if (s == 4) {
        if (act) {
            float a = sb[0];
            #pragma unroll
            for (int dd = 0; dd < DD; dd++) a = fmaf(y[dd], sW[dd], a);
            outp[g] = a;
        }
        return;
    }

    float o_[DD];
    #pragma unroll
    for (int o = 0; o < DD; o++) {
        float a = sb[o];
        #pragma unroll
        for (int dd = 0; dd < DD; dd++) a = fmaf(sW[o * DD + dd], y[dd], a);
        o_[o] = act ? a : 0.f;
        if (act) d_t[g * DD + o] = a;
    }

    float ls[DD], lq[DD];
    #pragma unroll
    for (int o = 0; o < DD; o++) {
        ls[o] = o_[o]; lq[o] = o_[o] * o_[o];
        #pragma unroll
        for (int off = 16; off > 0; off >>= 1) {
            ls[o] += __shfl_xor_sync(0xffffffffu, ls[o], off);
            lq[o] += __shfl_xor_sync(0xffffffffu, lq[o], off);
        }
    }
    if (lid < DD)          sred[wid][lid] = ls[lid];
    else if (lid < 2 * DD) sred[wid][lid] = lq[lid - DD];
    __syncthreads();
    if (tid < 2 * DD) {
        float a = 0.f;
        #pragma unroll
        for (int w = 0; w < NHT / 32; w++) a += sred[w][tid];
        atomicAdd(&d_stats[s * 2 * DD + tid], a);
    }
}

extern "C" void kernel_launch(void* const* d_in, const int* in_sizes, int n_in,
                              void* d_out, int out_size) {
    const float* x     = (const float*)d_in[0];
    const int*   ei32  = (const int*)d_in[1];
    const float* attr  = (const float*)d_in[2];
    const int*   b32   = (const int*)d_in[3];
    const float* fc1_w  = (const float*)d_in[4],  *fc1_b  = (const float*)d_in[5];
    const float* fc2_w  = (const float*)d_in[6],  *fc2_b  = (const float*)d_in[7];
    const float* rfc1_w = (const float*)d_in[8],  *rfc1_b = (const float*)d_in[9];
    const float* rfc2_w = (const float*)d_in[10], *rfc2_b = (const float*)d_in[11];
    const float* fco_w  = (const float*)d_in[12], *fco_b  = (const float*)d_in[13];
    const float* bn1_g  = (const float*)d_in[14], *bn1_b  = (const float*)d_in[15];
    const float* bn2_g  = (const float*)d_in[16], *bn2_b  = (const float*)d_in[17];
    const float* rbn1_g = (const float*)d_in[18], *rbn1_b = (const float*)d_in[19];
    const float* rbn2_g = (const float*)d_in[20], *rbn2_b = (const float*)d_in[21];
    float* out = (float*)d_out;

    k_init<<<(GG * DD + 255) / 256, 256>>>(ei32);
    k_scat<<<(EE + 511) / 512, 512>>>(x, ei32, attr, b32);
    k_gath<<<(GG * SL * 32 + 1023) / 1024, 1024>>>(x);

    k_stage<<<NHB, NHT>>>(0, fc1_w,  fc1_b,  nullptr, nullptr, b32,     nullptr);
    k_stage<<<NHB, NHT>>>(1, fc2_w,  fc2_b,  bn1_g,  bn1_b,  nullptr, nullptr);
    k_stage<<<NHB, NHT>>>(2, rfc1_w, rfc1_b, bn2_g,  bn2_b,  nullptr, nullptr);
    k_stage<<<NHB, NHT>>>(3, rfc2_w, rfc2_b, rbn1_g, rbn1_b, nullptr, nullptr);
    k_stage<<<NHB, NHT>>>(4, fco_w,  fco_b,  rbn2_g, rbn2_b, nullptr, out);
}